// round 3
// baseline (speedup 1.0000x reference)
#include <cuda_runtime.h>

// Problem constants (fixed-shape dataset)
#define NN 100000   // nodes
#define NE 600000   // edges
#define DD 128      // embed dim
#define NG 1000     // graphs
#define NL 3        // gcn layers

#define SCAN_BLK 256
#define NBLK ((NN + SCAN_BLK - 1) / SCAN_BLK)   // 391

// Scratch (device globals: allocation-free per harness rules)
__device__ float g_bufA[(size_t)NN * DD];   // aggregated layer output
__device__ float g_bufB[(size_t)NN * DD];   // transform output (h @ W)
__device__ float g_dinv[NN];                // rsqrt(deg+1)
__device__ float g_s[NN];                   // per-node score
__device__ int   g_counts[NN];              // in-degree histogram
__device__ int   g_cursor[NN];              // placement cursors
__device__ int   g_offs[NN + 1];            // CSR offsets
__device__ int   g_part[NBLK];              // scan partials
__device__ int   g_partx[NBLK];             // scanned partials (exclusive)
__device__ int2  g_sorted[NE];              // (src, bitcast(edge_norm)) grouped by dst

typedef unsigned long long u64;

__device__ __forceinline__ u64 fma2(u64 a, u64 b, u64 c) {
    u64 d;
    asm("fma.rn.f32x2 %0, %1, %2, %3;" : "=l"(d) : "l"(a), "l"(b), "l"(c));
    return d;
}
__device__ __forceinline__ u64 pack2(float x, float y) {
    u64 d;
    asm("mov.b64 %0, {%1, %2};" : "=l"(d) : "f"(x), "f"(y));
    return d;
}
__device__ __forceinline__ float2 unpack2(u64 v) {
    float2 r;
    asm("mov.b64 {%0, %1}, %2;" : "=f"(r.x), "=f"(r.y) : "l"(v));
    return r;
}

// ---------------------------------------------------------------------------
// CSR build: histogram -> 3-phase scan -> place
// ---------------------------------------------------------------------------
__global__ void k_zero_int(int* p, int n) {
    int i = blockIdx.x * blockDim.x + threadIdx.x;
    if (i < n) p[i] = 0;
}

__global__ void k_hist(const int* __restrict__ dst, int* __restrict__ counts) {
    int e = blockIdx.x * blockDim.x + threadIdx.x;
    if (e < NE) atomicAdd(&counts[dst[e]], 1);
}

__global__ void k_dinv(const int* __restrict__ counts, float* __restrict__ dinv) {
    int i = blockIdx.x * blockDim.x + threadIdx.x;
    if (i < NN) dinv[i] = rsqrtf((float)counts[i] + 1.0f);
}

// phase 1: per-block sums
__global__ __launch_bounds__(SCAN_BLK) void k_reduce(const int* __restrict__ counts,
                                                     int* __restrict__ part)
{
    __shared__ int sh[8];
    const int tid = threadIdx.x;
    const int lane = tid & 31;
    const int wid = tid >> 5;
    int i = blockIdx.x * SCAN_BLK + tid;
    int v = (i < NN) ? counts[i] : 0;
#pragma unroll
    for (int o = 16; o > 0; o >>= 1) v += __shfl_xor_sync(0xffffffffu, v, o);
    if (lane == 0) sh[wid] = v;
    __syncthreads();
    if (wid == 0) {
        int s = (lane < 8) ? sh[lane] : 0;
#pragma unroll
        for (int o = 4; o > 0; o >>= 1) s += __shfl_xor_sync(0xffffffffu, s, o);
        if (lane == 0) part[blockIdx.x] = s;
    }
}

// phase 2: scan the 391 partials in one block (512 threads)
__global__ __launch_bounds__(512) void k_scanpart(const int* __restrict__ part,
                                                  int* __restrict__ partx)
{
    __shared__ int wsum[16];
    const int tid = threadIdx.x;
    const int lane = tid & 31;
    const int wid = tid >> 5;
    int v = (tid < NBLK) ? part[tid] : 0;
    int x = v;
#pragma unroll
    for (int o = 1; o < 32; o <<= 1) {
        int y = __shfl_up_sync(0xffffffffu, x, o);
        if (lane >= o) x += y;
    }
    if (lane == 31) wsum[wid] = x;
    __syncthreads();
    if (wid == 0) {
        int s = (lane < 16) ? wsum[lane] : 0;
#pragma unroll
        for (int o = 1; o < 16; o <<= 1) {
            int y = __shfl_up_sync(0xffffffffu, s, o);
            if (lane >= o) s += y;
        }
        if (lane < 16) wsum[lane] = s;
    }
    __syncthreads();
    int excl = x - v + ((wid > 0) ? wsum[wid - 1] : 0);
    if (tid < NBLK) partx[tid] = excl;
}

// phase 3: per-block scan + add block offset
__global__ __launch_bounds__(SCAN_BLK) void k_apply(const int* __restrict__ counts,
                                                    const int* __restrict__ partx,
                                                    int* __restrict__ offs,
                                                    int* __restrict__ cursor)
{
    __shared__ int wsum[8];
    const int tid = threadIdx.x;
    const int lane = tid & 31;
    const int wid = tid >> 5;
    int i = blockIdx.x * SCAN_BLK + tid;
    int v = (i < NN) ? counts[i] : 0;
    int x = v;
#pragma unroll
    for (int o = 1; o < 32; o <<= 1) {
        int y = __shfl_up_sync(0xffffffffu, x, o);
        if (lane >= o) x += y;
    }
    if (lane == 31) wsum[wid] = x;
    __syncthreads();
    if (wid == 0) {
        int s = (lane < 8) ? wsum[lane] : 0;
#pragma unroll
        for (int o = 1; o < 8; o <<= 1) {
            int y = __shfl_up_sync(0xffffffffu, s, o);
            if (lane >= o) s += y;
        }
        if (lane < 8) wsum[lane] = s;
    }
    __syncthreads();
    int excl = partx[blockIdx.x] + x - v + ((wid > 0) ? wsum[wid - 1] : 0);
    if (i < NN) { offs[i] = excl; cursor[i] = excl; }
    if (i == NN - 1) offs[NN] = excl + v;
}

__global__ void k_place(const int* __restrict__ src, const int* __restrict__ dst,
                        const float* __restrict__ dinv,
                        int* __restrict__ cursor, int2* __restrict__ sorted)
{
    int e = blockIdx.x * blockDim.x + threadIdx.x;
    if (e >= NE) return;
    int s = src[e];
    int d = dst[e];
    float en = dinv[s] * dinv[d];
    int pos = atomicAdd(&cursor[d], 1);
    sorted[pos] = make_int2(s, __float_as_int(en));
}

// ---------------------------------------------------------------------------
// GEMM: C[n x 128] = A[n x 128] @ W[128 x 128]
// BM=64, BN=128, BK=16, 256 threads, 8x4 outputs/thread, f32x2 FMA.
// A stored pre-duplicated in shared as (a,a) u64 pairs -> no packs in hot loop.
// ---------------------------------------------------------------------------
__global__ __launch_bounds__(256) void k_gemm(const float* __restrict__ A,
                                              const float* __restrict__ W,
                                              float* __restrict__ C, int n)
{
    __shared__ __align__(16) u64 As2[16][64];     // (a,a) pairs
    __shared__ __align__(16) float Bs[16][128];

    const int tid = threadIdx.x;
    const int tx = tid & 31;
    const int ty = tid >> 5;
    const int r0 = blockIdx.x * 64;

    u64 acc[8][2];
#pragma unroll
    for (int i = 0; i < 8; i++) { acc[i][0] = 0ull; acc[i][1] = 0ull; }

    const int arow = tid >> 2;
    const int acol4 = tid & 3;
    const int grow = r0 + arow;

    for (int kk = 0; kk < 128; kk += 16) {
        float4 av = make_float4(0.f, 0.f, 0.f, 0.f);
        if (grow < n)
            av = *(const float4*)(A + (size_t)grow * DD + kk + acol4 * 4);
        As2[acol4 * 4 + 0][arow] = pack2(av.x, av.x);
        As2[acol4 * 4 + 1][arow] = pack2(av.y, av.y);
        As2[acol4 * 4 + 2][arow] = pack2(av.z, av.z);
        As2[acol4 * 4 + 3][arow] = pack2(av.w, av.w);

#pragma unroll
        for (int p = 0; p < 2; p++) {
            int idx = tid + 256 * p;
            int brow = idx >> 5;
            int bcol = (idx & 31) * 4;
            *(float4*)&Bs[brow][bcol] =
                *(const float4*)(W + (size_t)(kk + brow) * DD + bcol);
        }
        __syncthreads();

#pragma unroll
        for (int k = 0; k < 16; k++) {
            ulonglong2 b = *(const ulonglong2*)&Bs[k][tx * 4];
            ulonglong2 a01 = *(const ulonglong2*)&As2[k][ty * 8 + 0];
            ulonglong2 a23 = *(const ulonglong2*)&As2[k][ty * 8 + 2];
            ulonglong2 a45 = *(const ulonglong2*)&As2[k][ty * 8 + 4];
            ulonglong2 a67 = *(const ulonglong2*)&As2[k][ty * 8 + 6];
            acc[0][0] = fma2(a01.x, b.x, acc[0][0]); acc[0][1] = fma2(a01.x, b.y, acc[0][1]);
            acc[1][0] = fma2(a01.y, b.x, acc[1][0]); acc[1][1] = fma2(a01.y, b.y, acc[1][1]);
            acc[2][0] = fma2(a23.x, b.x, acc[2][0]); acc[2][1] = fma2(a23.x, b.y, acc[2][1]);
            acc[3][0] = fma2(a23.y, b.x, acc[3][0]); acc[3][1] = fma2(a23.y, b.y, acc[3][1]);
            acc[4][0] = fma2(a45.x, b.x, acc[4][0]); acc[4][1] = fma2(a45.x, b.y, acc[4][1]);
            acc[5][0] = fma2(a45.y, b.x, acc[5][0]); acc[5][1] = fma2(a45.y, b.y, acc[5][1]);
            acc[6][0] = fma2(a67.x, b.x, acc[6][0]); acc[6][1] = fma2(a67.x, b.y, acc[6][1]);
            acc[7][0] = fma2(a67.y, b.x, acc[7][0]); acc[7][1] = fma2(a67.y, b.y, acc[7][1]);
        }
        __syncthreads();
    }

#pragma unroll
    for (int i = 0; i < 8; i++) {
        int row = r0 + ty * 8 + i;
        if (row < n) {
            float2 lo = unpack2(acc[i][0]);
            float2 hi = unpack2(acc[i][1]);
            *(float4*)(C + (size_t)row * DD + tx * 4) = make_float4(lo.x, lo.y, hi.x, hi.y);
        }
    }
}

// ---------------------------------------------------------------------------
// gather-aggregate: one warp per node
// OUT[i] = relu?( H[i]*dinv[i]^2 + bias + sum_{e in CSR[i]} H[src_e]*en_e )
// ---------------------------------------------------------------------------
__global__ __launch_bounds__(256) void k_aggregate(const float* __restrict__ H,
                                                   const int* __restrict__ offs,
                                                   const int2* __restrict__ sorted,
                                                   const float* __restrict__ dinv,
                                                   const float* __restrict__ bias,
                                                   float* __restrict__ OUT,
                                                   int do_relu)
{
    int g = blockIdx.x * blockDim.x + threadIdx.x;
    int i = g >> 5;
    int lane = g & 31;
    if (i >= NN) return;

    float di = dinv[i];
    float sn = di * di;

    float4 h = *(const float4*)(H + (size_t)i * DD + lane * 4);
    float4 b = *(const float4*)(bias + lane * 4);
    float4 acc = make_float4(fmaf(h.x, sn, b.x), fmaf(h.y, sn, b.y),
                             fmaf(h.z, sn, b.z), fmaf(h.w, sn, b.w));

    int e0 = offs[i];
    int e1 = offs[i + 1];
    for (int e = e0; e < e1; e++) {
        int2 p = sorted[e];
        float en = __int_as_float(p.y);
        float4 v = *(const float4*)(H + (size_t)p.x * DD + lane * 4);
        acc.x = fmaf(v.x, en, acc.x);
        acc.y = fmaf(v.y, en, acc.y);
        acc.z = fmaf(v.z, en, acc.z);
        acc.w = fmaf(v.w, en, acc.w);
    }

    if (do_relu) {
        acc.x = fmaxf(acc.x, 0.f); acc.y = fmaxf(acc.y, 0.f);
        acc.z = fmaxf(acc.z, 0.f); acc.w = fmaxf(acc.w, 0.f);
    }
    *(float4*)(OUT + (size_t)i * DD + lane * 4) = acc;
}

// ---------------------------------------------------------------------------
// fused MLP head: s = relu(h @ W1 + b1) @ w2 + b2, mask -> per-node score
// ---------------------------------------------------------------------------
__global__ __launch_bounds__(256) void k_mlp(const float* __restrict__ A,
                                             const float* __restrict__ W1,
                                             const float* __restrict__ b1,
                                             const float* __restrict__ w2,
                                             const float* __restrict__ b2p,
                                             const int* __restrict__ mask,
                                             float* __restrict__ S, int n)
{
    __shared__ __align__(16) u64 As2[16][64];
    __shared__ __align__(16) float Bs[16][128];

    const int tid = threadIdx.x;
    const int tx = tid & 31;
    const int ty = tid >> 5;
    const int r0 = blockIdx.x * 64;

    u64 acc[8][2];
#pragma unroll
    for (int i = 0; i < 8; i++) { acc[i][0] = 0ull; acc[i][1] = 0ull; }

    const int arow = tid >> 2;
    const int acol4 = tid & 3;
    const int grow = r0 + arow;

    for (int kk = 0; kk < 128; kk += 16) {
        float4 av = make_float4(0.f, 0.f, 0.f, 0.f);
        if (grow < n)
            av = *(const float4*)(A + (size_t)grow * DD + kk + acol4 * 4);
        As2[acol4 * 4 + 0][arow] = pack2(av.x, av.x);
        As2[acol4 * 4 + 1][arow] = pack2(av.y, av.y);
        As2[acol4 * 4 + 2][arow] = pack2(av.z, av.z);
        As2[acol4 * 4 + 3][arow] = pack2(av.w, av.w);
#pragma unroll
        for (int p = 0; p < 2; p++) {
            int idx = tid + 256 * p;
            int brow = idx >> 5;
            int bcol = (idx & 31) * 4;
            *(float4*)&Bs[brow][bcol] =
                *(const float4*)(W1 + (size_t)(kk + brow) * DD + bcol);
        }
        __syncthreads();
#pragma unroll
        for (int k = 0; k < 16; k++) {
            ulonglong2 b = *(const ulonglong2*)&Bs[k][tx * 4];
            ulonglong2 a01 = *(const ulonglong2*)&As2[k][ty * 8 + 0];
            ulonglong2 a23 = *(const ulonglong2*)&As2[k][ty * 8 + 2];
            ulonglong2 a45 = *(const ulonglong2*)&As2[k][ty * 8 + 4];
            ulonglong2 a67 = *(const ulonglong2*)&As2[k][ty * 8 + 6];
            acc[0][0] = fma2(a01.x, b.x, acc[0][0]); acc[0][1] = fma2(a01.x, b.y, acc[0][1]);
            acc[1][0] = fma2(a01.y, b.x, acc[1][0]); acc[1][1] = fma2(a01.y, b.y, acc[1][1]);
            acc[2][0] = fma2(a23.x, b.x, acc[2][0]); acc[2][1] = fma2(a23.x, b.y, acc[2][1]);
            acc[3][0] = fma2(a23.y, b.x, acc[3][0]); acc[3][1] = fma2(a23.y, b.y, acc[3][1]);
            acc[4][0] = fma2(a45.x, b.x, acc[4][0]); acc[4][1] = fma2(a45.x, b.y, acc[4][1]);
            acc[5][0] = fma2(a45.y, b.x, acc[5][0]); acc[5][1] = fma2(a45.y, b.y, acc[5][1]);
            acc[6][0] = fma2(a67.x, b.x, acc[6][0]); acc[6][1] = fma2(a67.x, b.y, acc[6][1]);
            acc[7][0] = fma2(a67.y, b.x, acc[7][0]); acc[7][1] = fma2(a67.y, b.y, acc[7][1]);
        }
        __syncthreads();
    }

    float bv0 = b1[tx * 4 + 0], bv1 = b1[tx * 4 + 1], bv2 = b1[tx * 4 + 2], bv3 = b1[tx * 4 + 3];
    float wv0 = w2[tx * 4 + 0], wv1 = w2[tx * 4 + 1], wv2 = w2[tx * 4 + 2], wv3 = w2[tx * 4 + 3];
    float b2 = b2p[0];

#pragma unroll
    for (int i = 0; i < 8; i++) {
        float2 lo = unpack2(acc[i][0]);
        float2 hi = unpack2(acc[i][1]);
        float t = fmaxf(lo.x + bv0, 0.f) * wv0 + fmaxf(lo.y + bv1, 0.f) * wv1 +
                  fmaxf(hi.x + bv2, 0.f) * wv2 + fmaxf(hi.y + bv3, 0.f) * wv3;
#pragma unroll
        for (int off = 16; off > 0; off >>= 1)
            t += __shfl_xor_sync(0xffffffffu, t, off);
        if (tx == 0) {
            int row = r0 + ty * 8 + i;
            if (row < n) {
                float sv = t + b2;
                if (mask[row] == 0) sv = -1e9f;
                S[row] = sv;
            }
        }
    }
}

// ---------------------------------------------------------------------------
// per-graph segment softmax (batch is sorted) — one block per graph
// ---------------------------------------------------------------------------
__device__ __forceinline__ int lower_bound(const int* __restrict__ a, int n, int v) {
    int lo = 0, hi = n;
    while (lo < hi) {
        int mid = (lo + hi) >> 1;
        if (a[mid] < v) lo = mid + 1; else hi = mid;
    }
    return lo;
}

__global__ __launch_bounds__(256) void k_softmax(const float* __restrict__ S,
                                                 const int* __restrict__ batch,
                                                 float* __restrict__ out)
{
    __shared__ float red[256];
    __shared__ int seg[2];
    const int tid = threadIdx.x;
    const int g = blockIdx.x;

    if (tid == 0) {
        seg[0] = lower_bound(batch, NN, g);
        seg[1] = lower_bound(batch, NN, g + 1);
    }
    __syncthreads();
    const int start = seg[0], end = seg[1];
    if (start >= end) return;

    float m = -3.4e38f;
    for (int i = start + tid; i < end; i += 256) m = fmaxf(m, S[i]);
    red[tid] = m;
    __syncthreads();
    for (int o = 128; o > 0; o >>= 1) {
        if (tid < o) red[tid] = fmaxf(red[tid], red[tid + o]);
        __syncthreads();
    }
    m = red[0];
    __syncthreads();

    float z = 0.f;
    for (int i = start + tid; i < end; i += 256) z += expf(S[i] - m);
    red[tid] = z;
    __syncthreads();
    for (int o = 128; o > 0; o >>= 1) {
        if (tid < o) red[tid] += red[tid + o];
        __syncthreads();
    }
    z = red[0];

    float inv = 1.0f / z;
    for (int i = start + tid; i < end; i += 256) out[i] = expf(S[i] - m) * inv;
}

// ---------------------------------------------------------------------------
// launch
// ---------------------------------------------------------------------------
extern "C" void kernel_launch(void* const* d_in, const int* in_sizes, int n_in,
                              void* d_out, int out_size)
{
    const float* x       = (const float*)d_in[0];
    const int*   eidx    = (const int*)d_in[1];
    const int*   batch   = (const int*)d_in[2];
    const int*   mask    = (const int*)d_in[3];
    const float* gcn_w   = (const float*)d_in[4];
    const float* gcn_b   = (const float*)d_in[5];
    const float* lin1_w  = (const float*)d_in[6];
    const float* lin1_b  = (const float*)d_in[7];
    const float* lin2_w  = (const float*)d_in[8];
    const float* lin2_b  = (const float*)d_in[9];
    float* out = (float*)d_out;

    const int* src = eidx;
    const int* dst = eidx + NE;

    float *bufA, *bufB, *dinv, *sbuf;
    int *counts, *cursor, *offs, *part, *partx;
    int2 *sorted;
    cudaGetSymbolAddress((void**)&bufA, g_bufA);
    cudaGetSymbolAddress((void**)&bufB, g_bufB);
    cudaGetSymbolAddress((void**)&dinv, g_dinv);
    cudaGetSymbolAddress((void**)&sbuf, g_s);
    cudaGetSymbolAddress((void**)&counts, g_counts);
    cudaGetSymbolAddress((void**)&cursor, g_cursor);
    cudaGetSymbolAddress((void**)&offs, g_offs);
    cudaGetSymbolAddress((void**)&part, g_part);
    cudaGetSymbolAddress((void**)&partx, g_partx);
    cudaGetSymbolAddress((void**)&sorted, g_sorted);

    // CSR build (once per launch)
    k_zero_int<<<(NN + 255) / 256, 256>>>(counts, NN);
    k_hist<<<(NE + 255) / 256, 256>>>(dst, counts);
    k_dinv<<<(NN + 255) / 256, 256>>>(counts, dinv);
    k_reduce<<<NBLK, SCAN_BLK>>>(counts, part);
    k_scanpart<<<1, 512>>>(part, partx);
    k_apply<<<NBLK, SCAN_BLK>>>(counts, partx, offs, cursor);
    k_place<<<(NE + 255) / 256, 256>>>(src, dst, dinv, cursor, sorted);

    const int gemm_blocks = (NN + 63) / 64;
    const int agg_blocks = (NN * 32 + 255) / 256;

    // GCN layers: gemm -> gather-aggregate (self-loop + bias + relu fused)
    const float* in_ptr = x;
    for (int l = 0; l < NL; l++) {
        k_gemm<<<gemm_blocks, 256>>>(in_ptr, gcn_w + (size_t)l * DD * DD, bufB, NN);
        k_aggregate<<<agg_blocks, 256>>>(bufB, offs, sorted, dinv,
                                         gcn_b + (size_t)l * DD, bufA,
                                         (l < NL - 1) ? 1 : 0);
        in_ptr = bufA;
    }

    // MLP head -> per-node score (mask folded in)
    k_mlp<<<gemm_blocks, 256>>>(bufA, lin1_w, lin1_b, lin2_w, lin2_b, mask, sbuf, NN);

    // per-graph softmax
    k_softmax<<<NG, 256>>>(sbuf, batch, out);
}

// round 4
// speedup vs baseline: 1.2803x; 1.2803x over previous
#include <cuda_runtime.h>

// Problem constants (fixed-shape dataset)
#define NN 100000   // nodes
#define NE 600000   // edges
#define DD 128      // embed dim
#define NG 1000     // graphs
#define NL 3        // gcn layers

#define SCAN_BLK 256
#define NBLK ((NN + SCAN_BLK - 1) / SCAN_BLK)   // 391

// Scratch (device globals: allocation-free per harness rules)
__device__ float g_bufA[(size_t)NN * DD];   // aggregated layer output
__device__ float g_bufB[(size_t)NN * DD];   // transform output (h @ W)
__device__ float g_dinv[NN];                // rsqrt(deg+1)
__device__ float g_s[NN];                   // per-node score
__device__ int   g_counts[NN];              // in-degree histogram
__device__ int   g_cursor[NN];              // placement cursors
__device__ int   g_offs[NN + 1];            // CSR offsets
__device__ int   g_part[NBLK];              // scan partials
__device__ int   g_partx[NBLK];             // scanned partials (exclusive)
__device__ int2  g_sorted[NE];              // (src, bitcast(edge_norm)) grouped by dst

typedef unsigned long long u64;

__device__ __forceinline__ u64 fma2(u64 a, u64 b, u64 c) {
    u64 d;
    asm("fma.rn.f32x2 %0, %1, %2, %3;" : "=l"(d) : "l"(a), "l"(b), "l"(c));
    return d;
}
__device__ __forceinline__ u64 pack2(float x, float y) {
    u64 d;
    asm("mov.b64 %0, {%1, %2};" : "=l"(d) : "f"(x), "f"(y));
    return d;
}
__device__ __forceinline__ float2 unpack2(u64 v) {
    float2 r;
    asm("mov.b64 {%0, %1}, %2;" : "=f"(r.x), "=f"(r.y) : "l"(v));
    return r;
}

// ---------------------------------------------------------------------------
// CSR build: histogram -> 3-phase scan -> place
// ---------------------------------------------------------------------------
__global__ void k_zero_int(int* p, int n) {
    int i = blockIdx.x * blockDim.x + threadIdx.x;
    if (i < n) p[i] = 0;
}

__global__ void k_hist(const int* __restrict__ dst, int* __restrict__ counts) {
    int e = blockIdx.x * blockDim.x + threadIdx.x;
    if (e < NE) atomicAdd(&counts[dst[e]], 1);
}

__global__ void k_dinv(const int* __restrict__ counts, float* __restrict__ dinv) {
    int i = blockIdx.x * blockDim.x + threadIdx.x;
    if (i < NN) dinv[i] = rsqrtf((float)counts[i] + 1.0f);
}

// phase 1: per-block sums
__global__ __launch_bounds__(SCAN_BLK) void k_reduce(const int* __restrict__ counts,
                                                     int* __restrict__ part)
{
    __shared__ int sh[8];
    const int tid = threadIdx.x;
    const int lane = tid & 31;
    const int wid = tid >> 5;
    int i = blockIdx.x * SCAN_BLK + tid;
    int v = (i < NN) ? counts[i] : 0;
#pragma unroll
    for (int o = 16; o > 0; o >>= 1) v += __shfl_xor_sync(0xffffffffu, v, o);
    if (lane == 0) sh[wid] = v;
    __syncthreads();
    if (wid == 0) {
        int s = (lane < 8) ? sh[lane] : 0;
#pragma unroll
        for (int o = 4; o > 0; o >>= 1) s += __shfl_xor_sync(0xffffffffu, s, o);
        if (lane == 0) part[blockIdx.x] = s;
    }
}

// phase 2: scan the 391 partials in one block (512 threads)
__global__ __launch_bounds__(512) void k_scanpart(const int* __restrict__ part,
                                                  int* __restrict__ partx)
{
    __shared__ int wsum[16];
    const int tid = threadIdx.x;
    const int lane = tid & 31;
    const int wid = tid >> 5;
    int v = (tid < NBLK) ? part[tid] : 0;
    int x = v;
#pragma unroll
    for (int o = 1; o < 32; o <<= 1) {
        int y = __shfl_up_sync(0xffffffffu, x, o);
        if (lane >= o) x += y;
    }
    if (lane == 31) wsum[wid] = x;
    __syncthreads();
    if (wid == 0) {
        int s = (lane < 16) ? wsum[lane] : 0;
#pragma unroll
        for (int o = 1; o < 16; o <<= 1) {
            int y = __shfl_up_sync(0xffffffffu, s, o);
            if (lane >= o) s += y;
        }
        if (lane < 16) wsum[lane] = s;
    }
    __syncthreads();
    int excl = x - v + ((wid > 0) ? wsum[wid - 1] : 0);
    if (tid < NBLK) partx[tid] = excl;
}

// phase 3: per-block scan + add block offset
__global__ __launch_bounds__(SCAN_BLK) void k_apply(const int* __restrict__ counts,
                                                    const int* __restrict__ partx,
                                                    int* __restrict__ offs,
                                                    int* __restrict__ cursor)
{
    __shared__ int wsum[8];
    const int tid = threadIdx.x;
    const int lane = tid & 31;
    const int wid = tid >> 5;
    int i = blockIdx.x * SCAN_BLK + tid;
    int v = (i < NN) ? counts[i] : 0;
    int x = v;
#pragma unroll
    for (int o = 1; o < 32; o <<= 1) {
        int y = __shfl_up_sync(0xffffffffu, x, o);
        if (lane >= o) x += y;
    }
    if (lane == 31) wsum[wid] = x;
    __syncthreads();
    if (wid == 0) {
        int s = (lane < 8) ? wsum[lane] : 0;
#pragma unroll
        for (int o = 1; o < 8; o <<= 1) {
            int y = __shfl_up_sync(0xffffffffu, s, o);
            if (lane >= o) s += y;
        }
        if (lane < 8) wsum[lane] = s;
    }
    __syncthreads();
    int excl = partx[blockIdx.x] + x - v + ((wid > 0) ? wsum[wid - 1] : 0);
    if (i < NN) { offs[i] = excl; cursor[i] = excl; }
    if (i == NN - 1) offs[NN] = excl + v;
}

__global__ void k_place(const int* __restrict__ src, const int* __restrict__ dst,
                        const float* __restrict__ dinv,
                        int* __restrict__ cursor, int2* __restrict__ sorted)
{
    int e = blockIdx.x * blockDim.x + threadIdx.x;
    if (e >= NE) return;
    int s = src[e];
    int d = dst[e];
    float en = dinv[s] * dinv[d];
    int pos = atomicAdd(&cursor[d], 1);
    sorted[pos] = make_int2(s, __float_as_int(en));
}

// ---------------------------------------------------------------------------
// GEMM: C[n x 128] = A[n x 128] @ W[128 x 128]
// BM=64, BN=128, BK=16, 256 threads, each thread 8x4 outputs, f32x2 FMA.
// (round-2 proven version: regs=64, 80.6us)
// ---------------------------------------------------------------------------
__global__ __launch_bounds__(256) void k_gemm(const float* __restrict__ A,
                                              const float* __restrict__ W,
                                              float* __restrict__ C, int n)
{
    __shared__ float As[16][64];
    __shared__ float Bs[16][128];

    const int tid = threadIdx.x;
    const int tx = tid & 31;
    const int ty = tid >> 5;
    const int r0 = blockIdx.x * 64;

    u64 acc[8][2];
#pragma unroll
    for (int i = 0; i < 8; i++) { acc[i][0] = 0ull; acc[i][1] = 0ull; }

    const int arow = tid >> 2;
    const int acol4 = tid & 3;
    const int grow = r0 + arow;

    for (int kk = 0; kk < 128; kk += 16) {
        float4 av = make_float4(0.f, 0.f, 0.f, 0.f);
        if (grow < n)
            av = *(const float4*)(A + (size_t)grow * DD + kk + acol4 * 4);
        As[acol4 * 4 + 0][arow] = av.x;
        As[acol4 * 4 + 1][arow] = av.y;
        As[acol4 * 4 + 2][arow] = av.z;
        As[acol4 * 4 + 3][arow] = av.w;

#pragma unroll
        for (int p = 0; p < 2; p++) {
            int idx = tid + 256 * p;
            int brow = idx >> 5;
            int bcol = (idx & 31) * 4;
            *(float4*)&Bs[brow][bcol] =
                *(const float4*)(W + (size_t)(kk + brow) * DD + bcol);
        }
        __syncthreads();

#pragma unroll
        for (int k = 0; k < 16; k++) {
            u64 b0 = *(const u64*)&Bs[k][tx * 4];
            u64 b1 = *(const u64*)&Bs[k][tx * 4 + 2];
            float4 a0 = *(const float4*)&As[k][ty * 8];
            float4 a1 = *(const float4*)&As[k][ty * 8 + 4];
            u64 a2;
            a2 = pack2(a0.x, a0.x); acc[0][0] = fma2(a2, b0, acc[0][0]); acc[0][1] = fma2(a2, b1, acc[0][1]);
            a2 = pack2(a0.y, a0.y); acc[1][0] = fma2(a2, b0, acc[1][0]); acc[1][1] = fma2(a2, b1, acc[1][1]);
            a2 = pack2(a0.z, a0.z); acc[2][0] = fma2(a2, b0, acc[2][0]); acc[2][1] = fma2(a2, b1, acc[2][1]);
            a2 = pack2(a0.w, a0.w); acc[3][0] = fma2(a2, b0, acc[3][0]); acc[3][1] = fma2(a2, b1, acc[3][1]);
            a2 = pack2(a1.x, a1.x); acc[4][0] = fma2(a2, b0, acc[4][0]); acc[4][1] = fma2(a2, b1, acc[4][1]);
            a2 = pack2(a1.y, a1.y); acc[5][0] = fma2(a2, b0, acc[5][0]); acc[5][1] = fma2(a2, b1, acc[5][1]);
            a2 = pack2(a1.z, a1.z); acc[6][0] = fma2(a2, b0, acc[6][0]); acc[6][1] = fma2(a2, b1, acc[6][1]);
            a2 = pack2(a1.w, a1.w); acc[7][0] = fma2(a2, b0, acc[7][0]); acc[7][1] = fma2(a2, b1, acc[7][1]);
        }
        __syncthreads();
    }

#pragma unroll
    for (int i = 0; i < 8; i++) {
        int row = r0 + ty * 8 + i;
        if (row < n) {
            float2 lo = unpack2(acc[i][0]);
            float2 hi = unpack2(acc[i][1]);
            *(float4*)(C + (size_t)row * DD + tx * 4) = make_float4(lo.x, lo.y, hi.x, hi.y);
        }
    }
}

// ---------------------------------------------------------------------------
// gather-aggregate: one warp per node
// OUT[i] = relu?( H[i]*dinv[i]^2 + bias + sum_{e in CSR[i]} H[src_e]*en_e )
// ---------------------------------------------------------------------------
__global__ __launch_bounds__(256) void k_aggregate(const float* __restrict__ H,
                                                   const int* __restrict__ offs,
                                                   const int2* __restrict__ sorted,
                                                   const float* __restrict__ dinv,
                                                   const float* __restrict__ bias,
                                                   float* __restrict__ OUT,
                                                   int do_relu)
{
    int g = blockIdx.x * blockDim.x + threadIdx.x;
    int i = g >> 5;
    int lane = g & 31;
    if (i >= NN) return;

    float di = dinv[i];
    float sn = di * di;

    float4 h = *(const float4*)(H + (size_t)i * DD + lane * 4);
    float4 b = *(const float4*)(bias + lane * 4);
    float4 acc = make_float4(fmaf(h.x, sn, b.x), fmaf(h.y, sn, b.y),
                             fmaf(h.z, sn, b.z), fmaf(h.w, sn, b.w));

    int e0 = offs[i];
    int e1 = offs[i + 1];
    for (int e = e0; e < e1; e++) {
        int2 p = sorted[e];
        float en = __int_as_float(p.y);
        float4 v = *(const float4*)(H + (size_t)p.x * DD + lane * 4);
        acc.x = fmaf(v.x, en, acc.x);
        acc.y = fmaf(v.y, en, acc.y);
        acc.z = fmaf(v.z, en, acc.z);
        acc.w = fmaf(v.w, en, acc.w);
    }

    if (do_relu) {
        acc.x = fmaxf(acc.x, 0.f); acc.y = fmaxf(acc.y, 0.f);
        acc.z = fmaxf(acc.z, 0.f); acc.w = fmaxf(acc.w, 0.f);
    }
    *(float4*)(OUT + (size_t)i * DD + lane * 4) = acc;
}

// ---------------------------------------------------------------------------
// fused MLP head: s = relu(h @ W1 + b1) @ w2 + b2, mask -> per-node score
// (round-2 proven version)
// ---------------------------------------------------------------------------
__global__ __launch_bounds__(256) void k_mlp(const float* __restrict__ A,
                                             const float* __restrict__ W1,
                                             const float* __restrict__ b1,
                                             const float* __restrict__ w2,
                                             const float* __restrict__ b2p,
                                             const int* __restrict__ mask,
                                             float* __restrict__ S, int n)
{
    __shared__ float As[16][64];
    __shared__ float Bs[16][128];

    const int tid = threadIdx.x;
    const int tx = tid & 31;
    const int ty = tid >> 5;
    const int r0 = blockIdx.x * 64;

    u64 acc[8][2];
#pragma unroll
    for (int i = 0; i < 8; i++) { acc[i][0] = 0ull; acc[i][1] = 0ull; }

    const int arow = tid >> 2;
    const int acol4 = tid & 3;
    const int grow = r0 + arow;

    for (int kk = 0; kk < 128; kk += 16) {
        float4 av = make_float4(0.f, 0.f, 0.f, 0.f);
        if (grow < n)
            av = *(const float4*)(A + (size_t)grow * DD + kk + acol4 * 4);
        As[acol4 * 4 + 0][arow] = av.x;
        As[acol4 * 4 + 1][arow] = av.y;
        As[acol4 * 4 + 2][arow] = av.z;
        As[acol4 * 4 + 3][arow] = av.w;
#pragma unroll
        for (int p = 0; p < 2; p++) {
            int idx = tid + 256 * p;
            int brow = idx >> 5;
            int bcol = (idx & 31) * 4;
            *(float4*)&Bs[brow][bcol] =
                *(const float4*)(W1 + (size_t)(kk + brow) * DD + bcol);
        }
        __syncthreads();
#pragma unroll
        for (int k = 0; k < 16; k++) {
            u64 b0 = *(const u64*)&Bs[k][tx * 4];
            u64 b1v = *(const u64*)&Bs[k][tx * 4 + 2];
            float4 a0 = *(const float4*)&As[k][ty * 8];
            float4 a1 = *(const float4*)&As[k][ty * 8 + 4];
            u64 a2;
            a2 = pack2(a0.x, a0.x); acc[0][0] = fma2(a2, b0, acc[0][0]); acc[0][1] = fma2(a2, b1v, acc[0][1]);
            a2 = pack2(a0.y, a0.y); acc[1][0] = fma2(a2, b0, acc[1][0]); acc[1][1] = fma2(a2, b1v, acc[1][1]);
            a2 = pack2(a0.z, a0.z); acc[2][0] = fma2(a2, b0, acc[2][0]); acc[2][1] = fma2(a2, b1v, acc[2][1]);
            a2 = pack2(a0.w, a0.w); acc[3][0] = fma2(a2, b0, acc[3][0]); acc[3][1] = fma2(a2, b1v, acc[3][1]);
            a2 = pack2(a1.x, a1.x); acc[4][0] = fma2(a2, b0, acc[4][0]); acc[4][1] = fma2(a2, b1v, acc[4][1]);
            a2 = pack2(a1.y, a1.y); acc[5][0] = fma2(a2, b0, acc[5][0]); acc[5][1] = fma2(a2, b1v, acc[5][1]);
            a2 = pack2(a1.z, a1.z); acc[6][0] = fma2(a2, b0, acc[6][0]); acc[6][1] = fma2(a2, b1v, acc[6][1]);
            a2 = pack2(a1.w, a1.w); acc[7][0] = fma2(a2, b0, acc[7][0]); acc[7][1] = fma2(a2, b1v, acc[7][1]);
        }
        __syncthreads();
    }

    float bv0 = b1[tx * 4 + 0], bv1 = b1[tx * 4 + 1], bv2 = b1[tx * 4 + 2], bv3 = b1[tx * 4 + 3];
    float wv0 = w2[tx * 4 + 0], wv1 = w2[tx * 4 + 1], wv2 = w2[tx * 4 + 2], wv3 = w2[tx * 4 + 3];
    float b2 = b2p[0];

#pragma unroll
    for (int i = 0; i < 8; i++) {
        float2 lo = unpack2(acc[i][0]);
        float2 hi = unpack2(acc[i][1]);
        float t = fmaxf(lo.x + bv0, 0.f) * wv0 + fmaxf(lo.y + bv1, 0.f) * wv1 +
                  fmaxf(hi.x + bv2, 0.f) * wv2 + fmaxf(hi.y + bv3, 0.f) * wv3;
#pragma unroll
        for (int off = 16; off > 0; off >>= 1)
            t += __shfl_xor_sync(0xffffffffu, t, off);
        if (tx == 0) {
            int row = r0 + ty * 8 + i;
            if (row < n) {
                float sv = t + b2;
                if (mask[row] == 0) sv = -1e9f;
                S[row] = sv;
            }
        }
    }
}

// ---------------------------------------------------------------------------
// per-graph segment softmax (batch is sorted) — one block per graph
// ---------------------------------------------------------------------------
__device__ __forceinline__ int lower_bound(const int* __restrict__ a, int n, int v) {
    int lo = 0, hi = n;
    while (lo < hi) {
        int mid = (lo + hi) >> 1;
        if (a[mid] < v) lo = mid + 1; else hi = mid;
    }
    return lo;
}

__global__ __launch_bounds__(256) void k_softmax(const float* __restrict__ S,
                                                 const int* __restrict__ batch,
                                                 float* __restrict__ out)
{
    __shared__ float red[256];
    __shared__ int seg[2];
    const int tid = threadIdx.x;
    const int g = blockIdx.x;

    if (tid == 0) {
        seg[0] = lower_bound(batch, NN, g);
        seg[1] = lower_bound(batch, NN, g + 1);
    }
    __syncthreads();
    const int start = seg[0], end = seg[1];
    if (start >= end) return;

    float m = -3.4e38f;
    for (int i = start + tid; i < end; i += 256) m = fmaxf(m, S[i]);
    red[tid] = m;
    __syncthreads();
    for (int o = 128; o > 0; o >>= 1) {
        if (tid < o) red[tid] = fmaxf(red[tid], red[tid + o]);
        __syncthreads();
    }
    m = red[0];
    __syncthreads();

    float z = 0.f;
    for (int i = start + tid; i < end; i += 256) z += expf(S[i] - m);
    red[tid] = z;
    __syncthreads();
    for (int o = 128; o > 0; o >>= 1) {
        if (tid < o) red[tid] += red[tid + o];
        __syncthreads();
    }
    z = red[0];

    float inv = 1.0f / z;
    for (int i = start + tid; i < end; i += 256) out[i] = expf(S[i] - m) * inv;
}

// ---------------------------------------------------------------------------
// launch
// ---------------------------------------------------------------------------
extern "C" void kernel_launch(void* const* d_in, const int* in_sizes, int n_in,
                              void* d_out, int out_size)
{
    const float* x       = (const float*)d_in[0];
    const int*   eidx    = (const int*)d_in[1];
    const int*   batch   = (const int*)d_in[2];
    const int*   mask    = (const int*)d_in[3];
    const float* gcn_w   = (const float*)d_in[4];
    const float* gcn_b   = (const float*)d_in[5];
    const float* lin1_w  = (const float*)d_in[6];
    const float* lin1_b  = (const float*)d_in[7];
    const float* lin2_w  = (const float*)d_in[8];
    const float* lin2_b  = (const float*)d_in[9];
    float* out = (float*)d_out;

    const int* src = eidx;
    const int* dst = eidx + NE;

    float *bufA, *bufB, *dinv, *sbuf;
    int *counts, *cursor, *offs, *part, *partx;
    int2 *sorted;
    cudaGetSymbolAddress((void**)&bufA, g_bufA);
    cudaGetSymbolAddress((void**)&bufB, g_bufB);
    cudaGetSymbolAddress((void**)&dinv, g_dinv);
    cudaGetSymbolAddress((void**)&sbuf, g_s);
    cudaGetSymbolAddress((void**)&counts, g_counts);
    cudaGetSymbolAddress((void**)&cursor, g_cursor);
    cudaGetSymbolAddress((void**)&offs, g_offs);
    cudaGetSymbolAddress((void**)&part, g_part);
    cudaGetSymbolAddress((void**)&partx, g_partx);
    cudaGetSymbolAddress((void**)&sorted, g_sorted);

    // CSR build (once per launch)
    k_zero_int<<<(NN + 255) / 256, 256>>>(counts, NN);
    k_hist<<<(NE + 255) / 256, 256>>>(dst, counts);
    k_dinv<<<(NN + 255) / 256, 256>>>(counts, dinv);
    k_reduce<<<NBLK, SCAN_BLK>>>(counts, part);
    k_scanpart<<<1, 512>>>(part, partx);
    k_apply<<<NBLK, SCAN_BLK>>>(counts, partx, offs, cursor);
    k_place<<<(NE + 255) / 256, 256>>>(src, dst, dinv, cursor, sorted);

    const int gemm_blocks = (NN + 63) / 64;
    const int agg_blocks = (NN * 32 + 255) / 256;

    // GCN layers: gemm -> gather-aggregate (self-loop + bias + relu fused)
    const float* in_ptr = x;
    for (int l = 0; l < NL; l++) {
        k_gemm<<<gemm_blocks, 256>>>(in_ptr, gcn_w + (size_t)l * DD * DD, bufB, NN);
        k_aggregate<<<agg_blocks, 256>>>(bufB, offs, sorted, dinv,
                                         gcn_b + (size_t)l * DD, bufA,
                                         (l < NL - 1) ? 1 : 0);
        in_ptr = bufA;
    }

    // MLP head -> per-node score (mask folded in)
    k_mlp<<<gemm_blocks, 256>>>(bufA, lin1_w, lin1_b, lin2_w, lin2_b, mask, sbuf, NN);

    // per-graph softmax
    k_softmax<<<NG, 256>>>(sbuf, batch, out);
}

// round 6
// speedup vs baseline: 1.5979x; 1.2480x over previous
#include <cuda_runtime.h>
#include <cuda_bf16.h>
#include <cstdint>

// Problem constants (fixed-shape dataset)
#define NN 100000   // nodes
#define NE 600000   // edges
#define DD 128      // embed dim
#define NG 1000     // graphs
#define NL 3        // gcn layers

#define SCAN_BLK 256
#define NBLK ((NN + SCAN_BLK - 1) / SCAN_BLK)   // 391

#define GEMM_TILES ((NN + 127) / 128)           // 782

// padded smem row stride (bf16 elements) for ldmatrix tiles
#define TP 136
#define TILE_USH (128 * TP)                      // 17408 ushorts = 34816 B
#define SMEMSZ (4 * TILE_USH * 2)                // 139264 B

// Scratch (device globals: allocation-free per harness rules)
__device__ float g_bufA[(size_t)NN * DD];   // aggregated layer output
__device__ float g_bufB[(size_t)NN * DD];   // transform output (h @ W)
__device__ float g_dinv[NN];                // rsqrt(deg+1)
__device__ float g_s[NN];                   // per-node score
__device__ int   g_counts[NN];              // in-degree histogram
__device__ int   g_cursor[NN];              // placement cursors
__device__ int   g_offs[NN + 1];            // CSR offsets
__device__ int   g_part[NBLK];              // scan partials
__device__ int   g_partx[NBLK];             // scanned partials (exclusive)
__device__ int2  g_sorted[NE];              // (src, bitcast(edge_norm)) grouped by dst
// weight tiles, transposed [n][k] row-major bf16 hi/lo: [4 matrices][16384]
__device__ unsigned short g_wbhi[4 * 16384];
__device__ unsigned short g_wblo[4 * 16384];

__device__ __forceinline__ uint32_t smem_u32(const void* p) {
    uint32_t a;
    asm("{ .reg .u64 t; cvta.to.shared.u64 t, %1; cvt.u32.u64 %0, t; }" : "=r"(a) : "l"(p));
    return a;
}

__device__ __forceinline__ void ldsm_x4(uint32_t* r, uint32_t addr) {
    asm volatile("ldmatrix.sync.aligned.m8n8.x4.shared.b16 {%0,%1,%2,%3}, [%4];"
                 : "=r"(r[0]), "=r"(r[1]), "=r"(r[2]), "=r"(r[3]) : "r"(addr));
}

__device__ __forceinline__ void mma_bf16(float* d, const uint32_t* a,
                                         uint32_t b0, uint32_t b1) {
    asm volatile(
        "mma.sync.aligned.m16n8k16.row.col.f32.bf16.bf16.f32 "
        "{%0,%1,%2,%3}, {%4,%5,%6,%7}, {%8,%9}, {%0,%1,%2,%3};"
        : "+f"(d[0]), "+f"(d[1]), "+f"(d[2]), "+f"(d[3])
        : "r"(a[0]), "r"(a[1]), "r"(a[2]), "r"(a[3]), "r"(b0), "r"(b1));
}

// ---------------------------------------------------------------------------
// CSR build: histogram -> 3-phase scan -> place
// ---------------------------------------------------------------------------
__global__ void k_zero_int(int* p, int n) {
    int i = blockIdx.x * blockDim.x + threadIdx.x;
    if (i < n) p[i] = 0;
}

__global__ void k_hist(const int* __restrict__ dst, int* __restrict__ counts) {
    int e = blockIdx.x * blockDim.x + threadIdx.x;
    if (e < NE) atomicAdd(&counts[dst[e]], 1);
}

__global__ void k_dinv(const int* __restrict__ counts, float* __restrict__ dinv) {
    int i = blockIdx.x * blockDim.x + threadIdx.x;
    if (i < NN) dinv[i] = rsqrtf((float)counts[i] + 1.0f);
}

__global__ __launch_bounds__(SCAN_BLK) void k_reduce(const int* __restrict__ counts,
                                                     int* __restrict__ part)
{
    __shared__ int sh[8];
    const int tid = threadIdx.x;
    const int lane = tid & 31;
    const int wid = tid >> 5;
    int i = blockIdx.x * SCAN_BLK + tid;
    int v = (i < NN) ? counts[i] : 0;
#pragma unroll
    for (int o = 16; o > 0; o >>= 1) v += __shfl_xor_sync(0xffffffffu, v, o);
    if (lane == 0) sh[wid] = v;
    __syncthreads();
    if (wid == 0) {
        int s = (lane < 8) ? sh[lane] : 0;
#pragma unroll
        for (int o = 4; o > 0; o >>= 1) s += __shfl_xor_sync(0xffffffffu, s, o);
        if (lane == 0) part[blockIdx.x] = s;
    }
}

__global__ __launch_bounds__(512) void k_scanpart(const int* __restrict__ part,
                                                  int* __restrict__ partx)
{
    __shared__ int wsum[16];
    const int tid = threadIdx.x;
    const int lane = tid & 31;
    const int wid = tid >> 5;
    int v = (tid < NBLK) ? part[tid] : 0;
    int x = v;
#pragma unroll
    for (int o = 1; o < 32; o <<= 1) {
        int y = __shfl_up_sync(0xffffffffu, x, o);
        if (lane >= o) x += y;
    }
    if (lane == 31) wsum[wid] = x;
    __syncthreads();
    if (wid == 0) {
        int s = (lane < 16) ? wsum[lane] : 0;
#pragma unroll
        for (int o = 1; o < 16; o <<= 1) {
            int y = __shfl_up_sync(0xffffffffu, s, o);
            if (lane >= o) s += y;
        }
        if (lane < 16) wsum[lane] = s;
    }
    __syncthreads();
    int excl = x - v + ((wid > 0) ? wsum[wid - 1] : 0);
    if (tid < NBLK) partx[tid] = excl;
}

__global__ __launch_bounds__(SCAN_BLK) void k_apply(const int* __restrict__ counts,
                                                    const int* __restrict__ partx,
                                                    int* __restrict__ offs,
                                                    int* __restrict__ cursor)
{
    __shared__ int wsum[8];
    const int tid = threadIdx.x;
    const int lane = tid & 31;
    const int wid = tid >> 5;
    int i = blockIdx.x * SCAN_BLK + tid;
    int v = (i < NN) ? counts[i] : 0;
    int x = v;
#pragma unroll
    for (int o = 1; o < 32; o <<= 1) {
        int y = __shfl_up_sync(0xffffffffu, x, o);
        if (lane >= o) x += y;
    }
    if (lane == 31) wsum[wid] = x;
    __syncthreads();
    if (wid == 0) {
        int s = (lane < 8) ? wsum[lane] : 0;
#pragma unroll
        for (int o = 1; o < 8; o <<= 1) {
            int y = __shfl_up_sync(0xffffffffu, s, o);
            if (lane >= o) s += y;
        }
        if (lane < 8) wsum[lane] = s;
    }
    __syncthreads();
    int excl = partx[blockIdx.x] + x - v + ((wid > 0) ? wsum[wid - 1] : 0);
    if (i < NN) { offs[i] = excl; cursor[i] = excl; }
    if (i == NN - 1) offs[NN] = excl + v;
}

__global__ void k_place(const int* __restrict__ src, const int* __restrict__ dst,
                        const float* __restrict__ dinv,
                        int* __restrict__ cursor, int2* __restrict__ sorted)
{
    int e = blockIdx.x * blockDim.x + threadIdx.x;
    if (e >= NE) return;
    int s = src[e];
    int d = dst[e];
    float en = dinv[s] * dinv[d];
    int pos = atomicAdd(&cursor[d], 1);
    sorted[pos] = make_int2(s, __float_as_int(en));
}

// ---------------------------------------------------------------------------
// weight prep: W[128x128] fp32 -> transposed B[n][k] bf16 hi/lo, row-major.
// ---------------------------------------------------------------------------
__global__ __launch_bounds__(256) void k_prepw(const float* __restrict__ gcn_w,
                                               const float* __restrict__ lin1_w,
                                               unsigned short* __restrict__ whi,
                                               unsigned short* __restrict__ wlo)
{
    int m = blockIdx.x;                       // 0..3
    const float* W = (m < 3) ? gcn_w + (size_t)m * 16384 : lin1_w;
    unsigned short* oh = whi + (size_t)m * 16384;
    unsigned short* ol = wlo + (size_t)m * 16384;
    for (int idx = threadIdx.x; idx < 16384; idx += 256) {
        int nrow = idx >> 7;                  // output col
        int k = idx & 127;                    // reduction index
        float v = W[(size_t)k * 128 + nrow];
        __nv_bfloat16 h = __float2bfloat16(v);
        __nv_bfloat16 l = __float2bfloat16(v - __bfloat162float(h));
        oh[idx] = __bfloat16_as_ushort(h);
        ol[idx] = __bfloat16_as_ushort(l);
    }
}

// ---------------------------------------------------------------------------
// mma.sync bf16 split-2 GEMM: C[n x 128] = A[n x 128] @ W   (fp32-grade)
// CTA: 128 rows, 8 warps; warp: M=16, N=128. 3 passes: hh + hl + lh.
// ---------------------------------------------------------------------------
__global__ __launch_bounds__(256) void k_gemm_mma(const float* __restrict__ A,
                                                  const unsigned short* __restrict__ whi,
                                                  const unsigned short* __restrict__ wlo,
                                                  float* __restrict__ C, int n)
{
    extern __shared__ __align__(16) unsigned short smem[];
    unsigned short* Ahi = smem;
    unsigned short* Alo = Ahi + TILE_USH;
    unsigned short* Bhi = Alo + TILE_USH;
    unsigned short* Blo = Bhi + TILE_USH;

    const int tid = threadIdx.x;
    const int wid = tid >> 5;
    const int lane = tid & 31;
    const int r0 = blockIdx.x * 128;
    const int wr = wid * 16;

    // ---- load weight tiles into padded smem (16 uint4 per thread per array)
    {
        const uint4* sh = (const uint4*)whi;
        const uint4* sl = (const uint4*)wlo;
#pragma unroll
        for (int p = 0; p < 8; p++) {
            int i = p * 256 + tid;            // 0..2047 uint4 (= row 0..127, 16 per row)
            int row = i >> 4;
            int c8 = i & 15;                  // 8-ushort chunk
            *(uint4*)(Bhi + row * TP + c8 * 8) = sh[i];
            *(uint4*)(Blo + row * TP + c8 * 8) = sl[i];
        }
    }

    // ---- convert A rows -> bf16 hi/lo padded tiles (zero-fill past n)
#pragma unroll
    for (int it = 0; it < 16; it++) {
        int idx = it * 256 + tid;             // 0..4095
        int row = idx >> 5;
        int c4 = idx & 31;
        int grow = r0 + row;
        float4 v = make_float4(0.f, 0.f, 0.f, 0.f);
        if (grow < n) v = *(const float4*)(A + (size_t)grow * DD + c4 * 4);

        __nv_bfloat16 h0 = __float2bfloat16(v.x);
        __nv_bfloat16 h1 = __float2bfloat16(v.y);
        __nv_bfloat16 h2 = __float2bfloat16(v.z);
        __nv_bfloat16 h3 = __float2bfloat16(v.w);
        __nv_bfloat16 l0 = __float2bfloat16(v.x - __bfloat162float(h0));
        __nv_bfloat16 l1 = __float2bfloat16(v.y - __bfloat162float(h1));
        __nv_bfloat16 l2 = __float2bfloat16(v.z - __bfloat162float(h2));
        __nv_bfloat16 l3 = __float2bfloat16(v.w - __bfloat162float(h3));

        uint2 hp, lp;
        hp.x = (uint32_t)__bfloat16_as_ushort(h0) | ((uint32_t)__bfloat16_as_ushort(h1) << 16);
        hp.y = (uint32_t)__bfloat16_as_ushort(h2) | ((uint32_t)__bfloat16_as_ushort(h3) << 16);
        lp.x = (uint32_t)__bfloat16_as_ushort(l0) | ((uint32_t)__bfloat16_as_ushort(l1) << 16);
        lp.y = (uint32_t)__bfloat16_as_ushort(l2) | ((uint32_t)__bfloat16_as_ushort(l3) << 16);
        *(uint2*)(Ahi + row * TP + c4 * 4) = hp;
        *(uint2*)(Alo + row * TP + c4 * 4) = lp;
    }

    __syncthreads();

    // ---- fragment base addresses (bytes, shared space)
    // A matrices: m=lane>>3: row = wr + (m&1)*8 + (lane&7); col base (m>>1)*8
    uint32_t a_row = (uint32_t)(wr + ((lane >> 3) & 1) * 8 + (lane & 7));
    uint32_t a_col = (uint32_t)((lane >> 4) * 8);
    uint32_t ahi_base = smem_u32(Ahi) + (a_row * TP + a_col) * 2;
    uint32_t alo_base = smem_u32(Alo) + (a_row * TP + a_col) * 2;
    // B matrices: row = n0 + (m>>1)*8 + (lane&7); col base (m&1)*8
    uint32_t b_row = (uint32_t)((lane >> 4) * 8 + (lane & 7));
    uint32_t b_col = (uint32_t)(((lane >> 3) & 1) * 8);
    uint32_t bhi_base = smem_u32(Bhi) + (b_row * TP + b_col) * 2;
    uint32_t blo_base = smem_u32(Blo) + (b_row * TP + b_col) * 2;

    float d[16][4];
#pragma unroll
    for (int i = 0; i < 16; i++)
#pragma unroll
        for (int j = 0; j < 4; j++) d[i][j] = 0.f;

#pragma unroll
    for (int ks = 0; ks < 8; ks++) {
        uint32_t koff = (uint32_t)(ks * 16) * 2;      // byte offset along k
        uint32_t ahi[4], alo[4];
        ldsm_x4(ahi, ahi_base + koff);
        ldsm_x4(alo, alo_base + koff);
#pragma unroll
        for (int nt2 = 0; nt2 < 8; nt2++) {
            uint32_t noff = (uint32_t)(nt2 * 16 * TP) * 2;   // 16 B-rows per pair
            uint32_t bh[4], bl[4];
            ldsm_x4(bh, bhi_base + noff + koff);
            ldsm_x4(bl, blo_base + noff + koff);
            // n-tile 2*nt2: frag {bh[0],bh[1]} / {bl[0],bl[1]}
            mma_bf16(d[2 * nt2],     ahi, bh[0], bh[1]);
            mma_bf16(d[2 * nt2],     ahi, bl[0], bl[1]);
            mma_bf16(d[2 * nt2],     alo, bh[0], bh[1]);
            // n-tile 2*nt2+1: frag {bh[2],bh[3]}
            mma_bf16(d[2 * nt2 + 1], ahi, bh[2], bh[3]);
            mma_bf16(d[2 * nt2 + 1], ahi, bl[2], bl[3]);
            mma_bf16(d[2 * nt2 + 1], alo, bh[2], bh[3]);
        }
    }

    // ---- epilogue: thread (g = lane>>2, t = lane&3)
    {
        int g = lane >> 2;
        int t = lane & 3;
        int row0 = r0 + wr + g;
        int row1 = row0 + 8;
#pragma unroll
        for (int nt = 0; nt < 16; nt++) {
            int col = nt * 8 + t * 2;
            if (row0 < n)
                *(float2*)(C + (size_t)row0 * DD + col) = make_float2(d[nt][0], d[nt][1]);
            if (row1 < n)
                *(float2*)(C + (size_t)row1 * DD + col) = make_float2(d[nt][2], d[nt][3]);
        }
    }
}

// ---------------------------------------------------------------------------
// gather-aggregate: one warp per node
// OUT[i] = relu?( H[i]*dinv[i]^2 + bias + sum_{e in CSR[i]} H[src_e]*en_e )
// ---------------------------------------------------------------------------
__global__ __launch_bounds__(256) void k_aggregate(const float* __restrict__ H,
                                                   const int* __restrict__ offs,
                                                   const int2* __restrict__ sorted,
                                                   const float* __restrict__ dinv,
                                                   const float* __restrict__ bias,
                                                   float* __restrict__ OUT,
                                                   int do_relu)
{
    int g = blockIdx.x * blockDim.x + threadIdx.x;
    int i = g >> 5;
    int lane = g & 31;
    if (i >= NN) return;

    float di = dinv[i];
    float sn = di * di;

    float4 h = *(const float4*)(H + (size_t)i * DD + lane * 4);
    float4 b = *(const float4*)(bias + lane * 4);
    float4 acc = make_float4(fmaf(h.x, sn, b.x), fmaf(h.y, sn, b.y),
                             fmaf(h.z, sn, b.z), fmaf(h.w, sn, b.w));

    int e0 = offs[i];
    int e1 = offs[i + 1];
    for (int e = e0; e < e1; e++) {
        int2 p = sorted[e];
        float en = __int_as_float(p.y);
        float4 v = *(const float4*)(H + (size_t)p.x * DD + lane * 4);
        acc.x = fmaf(v.x, en, acc.x);
        acc.y = fmaf(v.y, en, acc.y);
        acc.z = fmaf(v.z, en, acc.z);
        acc.w = fmaf(v.w, en, acc.w);
    }

    if (do_relu) {
        acc.x = fmaxf(acc.x, 0.f); acc.y = fmaxf(acc.y, 0.f);
        acc.z = fmaxf(acc.z, 0.f); acc.w = fmaxf(acc.w, 0.f);
    }
    *(float4*)(OUT + (size_t)i * DD + lane * 4) = acc;
}

// ---------------------------------------------------------------------------
// head: S[i] = relu(T[i,:] + b1) . w2 + b2, masked. (T = bufA @ W1)
// ---------------------------------------------------------------------------
__global__ __launch_bounds__(256) void k_head(const float* __restrict__ T,
                                              const float* __restrict__ b1,
                                              const float* __restrict__ w2,
                                              const float* __restrict__ b2p,
                                              const int* __restrict__ mask,
                                              float* __restrict__ S)
{
    int g = blockIdx.x * blockDim.x + threadIdx.x;
    int i = g >> 5;
    int lane = g & 31;
    if (i >= NN) return;

    float4 t = *(const float4*)(T + (size_t)i * DD + lane * 4);
    float4 bb = *(const float4*)(b1 + lane * 4);
    float4 ww = *(const float4*)(w2 + lane * 4);
    float v = fmaxf(t.x + bb.x, 0.f) * ww.x + fmaxf(t.y + bb.y, 0.f) * ww.y +
              fmaxf(t.z + bb.z, 0.f) * ww.z + fmaxf(t.w + bb.w, 0.f) * ww.w;
#pragma unroll
    for (int o = 16; o > 0; o >>= 1) v += __shfl_xor_sync(0xffffffffu, v, o);
    if (lane == 0) {
        float sv = v + b2p[0];
        if (mask[i] == 0) sv = -1e9f;
        S[i] = sv;
    }
}

// ---------------------------------------------------------------------------
// per-graph segment softmax (batch is sorted) — one block per graph
// ---------------------------------------------------------------------------
__device__ __forceinline__ int lower_bound(const int* __restrict__ a, int n, int v) {
    int lo = 0, hi = n;
    while (lo < hi) {
        int mid = (lo + hi) >> 1;
        if (a[mid] < v) lo = mid + 1; else hi = mid;
    }
    return lo;
}

__global__ __launch_bounds__(256) void k_softmax(const float* __restrict__ S,
                                                 const int* __restrict__ batch,
                                                 float* __restrict__ out)
{
    __shared__ float red[256];
    __shared__ int seg[2];
    const int tid = threadIdx.x;
    const int g = blockIdx.x;

    if (tid == 0) {
        seg[0] = lower_bound(batch, NN, g);
        seg[1] = lower_bound(batch, NN, g + 1);
    }
    __syncthreads();
    const int start = seg[0], end = seg[1];
    if (start >= end) return;

    float m = -3.4e38f;
    for (int i = start + tid; i < end; i += 256) m = fmaxf(m, S[i]);
    red[tid] = m;
    __syncthreads();
    for (int o = 128; o > 0; o >>= 1) {
        if (tid < o) red[tid] = fmaxf(red[tid], red[tid + o]);
        __syncthreads();
    }
    m = red[0];
    __syncthreads();

    float z = 0.f;
    for (int i = start + tid; i < end; i += 256) z += expf(S[i] - m);
    red[tid] = z;
    __syncthreads();
    for (int o = 128; o > 0; o >>= 1) {
        if (tid < o) red[tid] += red[tid + o];
        __syncthreads();
    }
    z = red[0];

    float inv = 1.0f / z;
    for (int i = start + tid; i < end; i += 256) out[i] = expf(S[i] - m) * inv;
}

// ---------------------------------------------------------------------------
// launch
// ---------------------------------------------------------------------------
extern "C" void kernel_launch(void* const* d_in, const int* in_sizes, int n_in,
                              void* d_out, int out_size)
{
    const float* x       = (const float*)d_in[0];
    const int*   eidx    = (const int*)d_in[1];
    const int*   batch   = (const int*)d_in[2];
    const int*   mask    = (const int*)d_in[3];
    const float* gcn_w   = (const float*)d_in[4];
    const float* gcn_b   = (const float*)d_in[5];
    const float* lin1_w  = (const float*)d_in[6];
    const float* lin1_b  = (const float*)d_in[7];
    const float* lin2_w  = (const float*)d_in[8];
    const float* lin2_b  = (const float*)d_in[9];
    float* out = (float*)d_out;

    const int* src = eidx;
    const int* dst = eidx + NE;

    float *bufA, *bufB, *dinv, *sbuf;
    int *counts, *cursor, *offs, *part, *partx;
    int2 *sorted;
    unsigned short *whi, *wlo;
    cudaGetSymbolAddress((void**)&bufA, g_bufA);
    cudaGetSymbolAddress((void**)&bufB, g_bufB);
    cudaGetSymbolAddress((void**)&dinv, g_dinv);
    cudaGetSymbolAddress((void**)&sbuf, g_s);
    cudaGetSymbolAddress((void**)&counts, g_counts);
    cudaGetSymbolAddress((void**)&cursor, g_cursor);
    cudaGetSymbolAddress((void**)&offs, g_offs);
    cudaGetSymbolAddress((void**)&part, g_part);
    cudaGetSymbolAddress((void**)&partx, g_partx);
    cudaGetSymbolAddress((void**)&sorted, g_sorted);
    cudaGetSymbolAddress((void**)&whi, g_wbhi);
    cudaGetSymbolAddress((void**)&wlo, g_wblo);

    cudaFuncSetAttribute(k_gemm_mma, cudaFuncAttributeMaxDynamicSharedMemorySize, SMEMSZ);

    // CSR build (once per launch)
    k_zero_int<<<(NN + 255) / 256, 256>>>(counts, NN);
    k_hist<<<(NE + 255) / 256, 256>>>(dst, counts);
    k_dinv<<<(NN + 255) / 256, 256>>>(counts, dinv);
    k_reduce<<<NBLK, SCAN_BLK>>>(counts, part);
    k_scanpart<<<1, 512>>>(part, partx);
    k_apply<<<NBLK, SCAN_BLK>>>(counts, partx, offs, cursor);
    k_place<<<(NE + 255) / 256, 256>>>(src, dst, dinv, cursor, sorted);

    // weight tiles (bf16 hi/lo, transposed)
    k_prepw<<<4, 256>>>(gcn_w, lin1_w, whi, wlo);

    const int agg_blocks = (NN * 32 + 255) / 256;

    // GCN layers: mma gemm -> gather-aggregate (self-loop + bias + relu fused)
    const float* in_ptr = x;
    for (int l = 0; l < NL; l++) {
        k_gemm_mma<<<GEMM_TILES, 256, SMEMSZ>>>(in_ptr,
                                                whi + (size_t)l * 16384,
                                                wlo + (size_t)l * 16384,
                                                bufB, NN);
        k_aggregate<<<agg_blocks, 256>>>(bufB, offs, sorted, dinv,
                                         gcn_b + (size_t)l * DD, bufA,
                                         (l < NL - 1) ? 1 : 0);
        in_ptr = bufA;
    }

    // MLP: T = bufA @ W1 via mma, then fused head
    k_gemm_mma<<<GEMM_TILES, 256, SMEMSZ>>>(bufA, whi + (size_t)3 * 16384,
                                            wlo + (size_t)3 * 16384, bufB, NN);
    k_head<<<agg_blocks, 256>>>(bufB, lin1_b, lin2_w, lin2_b, mask, sbuf);

    // per-graph softmax
    k_softmax<<<NG, 256>>>(sbuf, batch, out);
}